// round 3
// baseline (speedup 1.0000x reference)
#include <cuda_runtime.h>
#include <math.h>

// Problem constants
#define Bx 8
#define Sx 1024
#define Dx 1024
#define Hx 1024
#define G3x 3072           // 3*H
#define FHx 2816
#define Mx (Bx*Sx)         // 8192 rows
#define NBLK_GRU 128

typedef unsigned long long ull;

// packed fp32x2 helpers (Blackwell f32x2 pipe: 2x fp32 FMA throughput)
#define FMA2(acc, a, b) asm volatile("fma.rn.f32x2 %0, %1, %2, %0;" : "+l"(acc) : "l"(a), "l"(b))
#define ADD2(acc, v)    asm volatile("add.rn.f32x2 %0, %0, %1;" : "+l"(acc) : "l"(v))

static __device__ __forceinline__ ull pk2(float lo, float hi) {
    ull r; asm("mov.b64 %0, {%1, %2};" : "=l"(r) : "f"(lo), "f"(hi)); return r;
}
static __device__ __forceinline__ float2 up2(ull v) {
    float2 f; asm("mov.b64 {%0, %1}, %2;" : "=f"(f.x), "=f"(f.y) : "l"(v)); return f;
}

// ---------------- scratch (device globals; no allocation allowed) ----------
__device__ float g_hnorm[(size_t)Mx * Dx];              // 32 MB
__device__ float g_xg[(size_t)2 * Mx * G3x];            // 201 MB (per-dir input gates)
__device__ float g_hcat0[(size_t)Mx * 2 * Dx];          // 64 MB
__device__ float g_hcat1[(size_t)Mx * 2 * Dx];          // 64 MB
__device__ float g_hbuf[2 * 2 * Bx * Hx];               // [parity][dir][B*H]
__device__ float g_y[(size_t)Mx * Dx];                  // 32 MB
__device__ float g_hn[(size_t)Mx * Dx];                 // 32 MB
__device__ float g_gate[(size_t)Mx * FHx];              // 92 MB
__device__ float g_up[(size_t)Mx * FHx];                // 92 MB
__device__ unsigned g_bar[2];                           // [0]=cumulative count, [1]=released gen

// ---------------- rmsnorm: one block per row of 1024 -----------------------
__global__ void rmsnorm_k(const float* __restrict__ x, const float* __restrict__ w,
                          float* __restrict__ o)
{
    int row = blockIdx.x;
    const float* xr = x + (size_t)row * Dx;
    float s = 0.f;
    for (int i = threadIdx.x; i < Dx; i += blockDim.x) { float v = xr[i]; s += v * v; }
    __shared__ float sm[32];
    for (int off = 16; off; off >>= 1) s += __shfl_xor_sync(~0u, s, off);
    if ((threadIdx.x & 31) == 0) sm[threadIdx.x >> 5] = s;
    __syncthreads();
    if (threadIdx.x < 32) {
        float v = (threadIdx.x < (blockDim.x >> 5)) ? sm[threadIdx.x] : 0.f;
        for (int off = 16; off; off >>= 1) v += __shfl_xor_sync(~0u, v, off);
        if (threadIdx.x == 0) sm[0] = rsqrtf(v / (float)Dx + 1e-5f);
    }
    __syncthreads();
    float sc = sm[0];
    float* orow = o + (size_t)row * Dx;
    for (int i = threadIdx.x; i < Dx; i += blockDim.x) orow[i] = xr[i] * sc * w[i];
}

// ---------------- SGEMM: C[M,N] = A[M,K] @ B[N,K]^T (+bias[N]) (+res) ------
// 128x128 block tile, BK=8, 256 threads, 8x8 per-thread microtile using
// packed f32x2 FMAs (acc pairs along N).
__global__ __launch_bounds__(256) void sgemm_bt(
    const float* __restrict__ A, const float* __restrict__ Bm,
    const float* __restrict__ bias, const float* __restrict__ res,
    float* __restrict__ C, int M, int N, int K)
{
    __shared__ float As[8][128];
    __shared__ float Bs[8][128];
    int tid = threadIdx.x;
    int tx = tid & 15, ty = tid >> 4;
    int row0 = blockIdx.y * 128, col0 = blockIdx.x * 128;
    int lr = tid >> 1;            // 0..127
    int lc = (tid & 1) * 4;       // 0 or 4
    const float* Ap = A + (size_t)(row0 + lr) * K + lc;
    const float* Bp = Bm + (size_t)(col0 + lr) * K + lc;
    ull acc2[8][4];
#pragma unroll
    for (int i = 0; i < 8; i++)
#pragma unroll
        for (int j = 0; j < 4; j++) acc2[i][j] = 0ull;

    for (int k0 = 0; k0 < K; k0 += 8) {
        float4 a4 = *(const float4*)(Ap + k0);
        float4 b4 = *(const float4*)(Bp + k0);
        As[lc + 0][lr] = a4.x; As[lc + 1][lr] = a4.y; As[lc + 2][lr] = a4.z; As[lc + 3][lr] = a4.w;
        Bs[lc + 0][lr] = b4.x; Bs[lc + 1][lr] = b4.y; Bs[lc + 2][lr] = b4.z; Bs[lc + 3][lr] = b4.w;
        __syncthreads();
#pragma unroll
        for (int k = 0; k < 8; k++) {
            float4 a0 = *(const float4*)&As[k][ty * 8];
            float4 a1 = *(const float4*)&As[k][ty * 8 + 4];
            ulonglong2 bq0 = *(const ulonglong2*)&Bs[k][tx * 8];
            ulonglong2 bq1 = *(const ulonglong2*)&Bs[k][tx * 8 + 4];
            float ar[8] = {a0.x, a0.y, a0.z, a0.w, a1.x, a1.y, a1.z, a1.w};
            ull bp[4] = {bq0.x, bq0.y, bq1.x, bq1.y};
#pragma unroll
            for (int i = 0; i < 8; i++) {
                ull a2 = pk2(ar[i], ar[i]);
#pragma unroll
                for (int j = 0; j < 4; j++)
                    FMA2(acc2[i][j], a2, bp[j]);
            }
        }
        __syncthreads();
    }

#pragma unroll
    for (int i = 0; i < 8; i++) {
        int m = row0 + ty * 8 + i;
#pragma unroll
        for (int j = 0; j < 4; j++) {
            int n0 = col0 + tx * 8 + 2 * j;
            float2 v = up2(acc2[i][j]);
            if (bias) { v.x += bias[n0]; v.y += bias[n0 + 1]; }
            if (res)  { v.x += res[(size_t)m * N + n0]; v.y += res[(size_t)m * N + n0 + 1]; }
            *(float2*)&C[(size_t)m * N + n0] = v;
        }
    }
}

// ---------------- persistent bidirectional GRU recurrence -------------------
// grid = 128 blocks x 512 threads (<= SM count, 1 block/SM resources -> all
// resident, spin barrier is safe). dir = blockIdx.x>>6; each of 16 warps owns
// one hidden unit j. h state double-buffered in global; staged to smem per step.
__device__ __forceinline__ void grid_bar(unsigned step)
{
    __syncthreads();
    if (threadIdx.x == 0) {
        __threadfence();
        unsigned a = atomicAdd(&g_bar[0], 1u);
        if (a == NBLK_GRU * (step + 1u) - 1u) {
            __threadfence();
            *(volatile unsigned*)&g_bar[1] = step + 1u;
        } else {
            while (*(volatile unsigned*)&g_bar[1] <= step)
                asm volatile("nanosleep.u32 64;");
        }
        __threadfence();
    }
    __syncthreads();
}

__global__ __launch_bounds__(512, 1) void gru_persist(
    const float* __restrict__ w_hh,    // [2][3H][H]
    const float* __restrict__ b_hh,    // [2][3H]
    const float* __restrict__ xg,      // [2][M][3H]
    float* __restrict__ seq_out,       // [B][S][2H]
    float* __restrict__ hbuf)          // [2][2][B][H]
{
    __shared__ float hs[Bx * Hx];      // 32KB: this dir's full state
    const int tid = threadIdx.x, warp = tid >> 5, lane = tid & 31;
    const int dir = blockIdx.x >> 6;
    const int j = (blockIdx.x & 63) * 16 + warp;
    const float* wbase = w_hh + (size_t)dir * 3 * Hx * Hx;
    const float* wr = wbase + (size_t)j * Hx;
    const float* wz = wbase + (size_t)(Hx + j) * Hx;
    const float* wn = wbase + (size_t)(2 * Hx + j) * Hx;
    const float br = b_hh[dir * G3x + j];
    const float bz = b_hh[dir * G3x + Hx + j];
    const float bn = b_hh[dir * G3x + 2 * Hx + j];

    for (int t = 0; t < Sx; t++) {
        // stage h_{t-1} (this dir) into smem
        if (t == 0) {
            for (int i = tid; i < Bx * Hx; i += 512) hs[i] = 0.f;
        } else {
            const float4* hi = (const float4*)(hbuf + (t & 1) * 2 * Bx * Hx + dir * Bx * Hx);
            for (int i = tid; i < Bx * Hx / 4; i += 512) ((float4*)hs)[i] = hi[i];
        }
        __syncthreads();

        // 3 gate dots over H=1024 for 8 batches, packed 2 batches per f32x2
        ull racc[4] = {0,0,0,0}, zacc[4] = {0,0,0,0}, nacc[4] = {0,0,0,0};
        for (int i = lane; i < Hx; i += 32) {
            float wrv = wr[i], wzv = wz[i], wnv = wn[i];
            ull wr2 = pk2(wrv, wrv), wz2 = pk2(wzv, wzv), wn2 = pk2(wnv, wnv);
#pragma unroll
            for (int p = 0; p < 4; p++) {
                ull h2 = pk2(hs[(2 * p) * Hx + i], hs[(2 * p + 1) * Hx + i]);
                FMA2(racc[p], wr2, h2);
                FMA2(zacc[p], wz2, h2);
                FMA2(nacc[p], wn2, h2);
            }
        }
#pragma unroll
        for (int off = 16; off; off >>= 1) {
#pragma unroll
            for (int p = 0; p < 4; p++) {
                ull rv = __shfl_xor_sync(~0u, racc[p], off);
                ull zv = __shfl_xor_sync(~0u, zacc[p], off);
                ull nv = __shfl_xor_sync(~0u, nacc[p], off);
                ADD2(racc[p], rv); ADD2(zacc[p], zv); ADD2(nacc[p], nv);
            }
        }
        if (lane < 8) {
            int b = lane, p = b >> 1;
            float2 rp = up2(racc[p]), zp = up2(zacc[p]), np = up2(nacc[p]);
            float rs = (b & 1) ? rp.y : rp.x;
            float zs = (b & 1) ? zp.y : zp.x;
            float ns = (b & 1) ? np.y : np.x;
            int t_eff = dir ? (Sx - 1 - t) : t;
            const float* xp = xg + ((size_t)dir * Mx + (size_t)b * Sx + t_eff) * (size_t)G3x;
            float r = 1.f / (1.f + expf(-(xp[j] + rs + br)));
            float z = 1.f / (1.f + expf(-(xp[Hx + j] + zs + bz)));
            float n = tanhf(xp[2 * Hx + j] + r * (ns + bn));
            float hp = hs[b * Hx + j];
            float hv = (1.f - z) * n + z * hp;
            hbuf[((t + 1) & 1) * 2 * Bx * Hx + dir * Bx * Hx + b * Hx + j] = hv;
            seq_out[((size_t)b * Sx + t_eff) * (2 * Hx) + dir * Hx + j] = hv;
        }
        if (t < Sx - 1) grid_bar((unsigned)t);
    }
}

// ---------------- misc -------------------------------------------------------
__global__ void swiglu_k(float* __restrict__ g, const float* __restrict__ u, size_t n)
{
    size_t i = (size_t)blockIdx.x * blockDim.x + threadIdx.x;
    if (i < n) {
        float gv = g[i];
        g[i] = gv / (1.f + expf(-gv)) * u[i];
    }
}

// ---------------- launch -----------------------------------------------------
extern "C" void kernel_launch(void* const* d_in, const int* in_sizes, int n_in,
                              void* d_out, int out_size)
{
    const float* x       = (const float*)d_in[0];
    const float* gnw     = (const float*)d_in[1];
    const float* w_ih_l0 = (const float*)d_in[2];
    const float* w_hh_l0 = (const float*)d_in[3];
    const float* b_ih_l0 = (const float*)d_in[4];
    const float* b_hh_l0 = (const float*)d_in[5];
    const float* w_ih_l1 = (const float*)d_in[6];
    const float* w_hh_l1 = (const float*)d_in[7];
    const float* b_ih_l1 = (const float*)d_in[8];
    const float* b_hh_l1 = (const float*)d_in[9];
    const float* gow     = (const float*)d_in[10];
    const float* fnw     = (const float*)d_in[11];
    const float* w1      = (const float*)d_in[12];
    const float* w2      = (const float*)d_in[13];
    const float* w3      = (const float*)d_in[14];
    float* out = (float*)d_out;

    float *hnorm, *xg, *hcat0, *hcat1, *hbuf, *y, *hn, *gg, *uu;
    unsigned* bar;
    cudaGetSymbolAddress((void**)&hnorm, g_hnorm);
    cudaGetSymbolAddress((void**)&xg,    g_xg);
    cudaGetSymbolAddress((void**)&hcat0, g_hcat0);
    cudaGetSymbolAddress((void**)&hcat1, g_hcat1);
    cudaGetSymbolAddress((void**)&hbuf,  g_hbuf);
    cudaGetSymbolAddress((void**)&y,     g_y);
    cudaGetSymbolAddress((void**)&hn,    g_hn);
    cudaGetSymbolAddress((void**)&gg,    g_gate);
    cudaGetSymbolAddress((void**)&uu,    g_up);
    cudaGetSymbolAddress((void**)&bar,   g_bar);

    // 1) pre-norm
    rmsnorm_k<<<Mx, 256>>>(x, gnw, hnorm);

    // 2) layer-0 input gates (per direction): xg = hnorm @ w_ih^T + b_ih
    for (int dir = 0; dir < 2; dir++)
        sgemm_bt<<<dim3(G3x / 128, Mx / 128), 256>>>(
            hnorm, w_ih_l0 + (size_t)dir * G3x * Dx, b_ih_l0 + dir * G3x, nullptr,
            xg + (size_t)dir * Mx * G3x, Mx, G3x, Dx);

    // 3) layer-0 recurrence: one persistent kernel, grid barrier per step
    cudaMemsetAsync(bar, 0, 2 * sizeof(unsigned));
    gru_persist<<<NBLK_GRU, 512>>>(w_hh_l0, b_hh_l0, xg, hcat0, hbuf);

    // 4) layer-1 input gates: K = 2*Dx
    for (int dir = 0; dir < 2; dir++)
        sgemm_bt<<<dim3(G3x / 128, Mx / 128), 256>>>(
            hcat0, w_ih_l1 + (size_t)dir * G3x * 2 * Dx, b_ih_l1 + dir * G3x, nullptr,
            xg + (size_t)dir * Mx * G3x, Mx, G3x, 2 * Dx);

    // 5) layer-1 recurrence
    cudaMemsetAsync(bar, 0, 2 * sizeof(unsigned));
    gru_persist<<<NBLK_GRU, 512>>>(w_hh_l1, b_hh_l1, xg, hcat1, hbuf);

    // 6) output projection + residual 1: y = x + hcat1 @ gow^T
    sgemm_bt<<<dim3(Dx / 128, Mx / 128), 256>>>(
        hcat1, gow, nullptr, x, y, Mx, Dx, 2 * Dx);

    // 7) FFN pre-norm
    rmsnorm_k<<<Mx, 256>>>(y, fnw, hn);

    // 8) SwiGLU FFN
    sgemm_bt<<<dim3(FHx / 128, Mx / 128), 256>>>(hn, w1, nullptr, nullptr, gg, Mx, FHx, Dx);
    sgemm_bt<<<dim3(FHx / 128, Mx / 128), 256>>>(hn, w3, nullptr, nullptr, uu, Mx, FHx, Dx);
    swiglu_k<<<(int)(((size_t)Mx * FHx + 255) / 256), 256>>>(gg, uu, (size_t)Mx * FHx);

    // 9) down-proj + residual 2 -> final output
    sgemm_bt<<<dim3(Dx / 128, Mx / 128), 256>>>(gg, w2, nullptr, y, out, Mx, Dx, FHx);
}